// round 1
// baseline (speedup 1.0000x reference)
#include <cuda_runtime.h>
#include <math.h>

#define BATCH   4
#define N_SEQ   1024
#define D_MODEL 256
#define N_HEADS 8
#define D_HEAD  32
#define ATT_SCALE 0.17677669529663687f   // 1/sqrt(32)

// Scratch (device globals: no allocation allowed in kernel_launch)
__device__ float g_Q[BATCH * N_HEADS * N_SEQ * D_HEAD];   // [b,h,n,dk]
__device__ float g_K[BATCH * N_HEADS * N_SEQ * D_HEAD];
__device__ float g_V[BATCH * N_HEADS * N_SEQ * D_HEAD];
__device__ float g_AO[BATCH * N_SEQ * D_MODEL];           // attention out, [b,n,d]
__device__ float g_maskval[BATCH * N_SEQ];                // 0 or -inf per key

// ---------------------------------------------------------------------------
// Mask prep: detect storage dtype of the bool mask (int32 / float32 / uint8)
// by bit pattern, then expand to float additive mask (0 or -inf).
// Deterministic: pure function of input contents.
// ---------------------------------------------------------------------------
__global__ void prep_mask_kernel(const void* __restrict__ mraw) {
    __shared__ int s_mode;
    if (threadIdx.x == 0) {
        const unsigned int* mi = (const unsigned int*)mraw;
        int ok_int = 1, ok_float = 1;
        // 1024 ints is safe to read for all three candidate layouts
        // (uint8 layout: 4096 bytes = 1024 ints).
        for (int i = 0; i < 1024; i++) {
            unsigned int v = mi[i];
            if (v > 1u) ok_int = 0;
            if (v != 0u && v != 0x3F800000u) ok_float = 0;
        }
        s_mode = ok_int ? 0 : (ok_float ? 1 : 2);
    }
    __syncthreads();
    const int mode = s_mode;
    const float NEG_INF = __int_as_float(0xff800000);
    for (int i = threadIdx.x; i < BATCH * N_SEQ; i += blockDim.x) {
        int masked;
        if (mode == 0)      masked = ((const int*)mraw)[i] != 0;
        else if (mode == 1) masked = ((const unsigned int*)mraw)[i] != 0u;
        else                masked = ((const unsigned char*)mraw)[i] != 0;
        g_maskval[i] = masked ? NEG_INF : 0.0f;
    }
}

// ---------------------------------------------------------------------------
// GEMM: C[r,c] = sum_k A[r,k] * W[c,k] + bias[c]
// A: [4096, 256] row-major, W: [256, 256] row-major (K contiguous in both).
// Block tile 64x64, K-chunk 32, 256 threads (16x16), 4x4 per thread.
// bhnd=1: scatter output into [b,h,n,dk] layout; bhnd=0: plain [4096,256].
// ---------------------------------------------------------------------------
__global__ __launch_bounds__(256) void gemm_proj_kernel(
    const float* __restrict__ A, const float* __restrict__ W,
    const float* __restrict__ bias, float* __restrict__ out, int bhnd)
{
    __shared__ float As[32][68];   // [k][row] transposed
    __shared__ float Ws[32][68];   // [k][col] transposed

    const int tid = threadIdx.x;
    const int tx = tid & 15;
    const int ty = tid >> 4;
    const int rbase = blockIdx.x * 64;
    const int cbase = blockIdx.y * 64;

    float acc[4][4];
#pragma unroll
    for (int i = 0; i < 4; i++)
#pragma unroll
        for (int j = 0; j < 4; j++) acc[i][j] = 0.0f;

    for (int k0 = 0; k0 < D_MODEL; k0 += 32) {
#pragma unroll
        for (int q = 0; q < 2; q++) {
            int s = q * 256 + tid;
            int row = s >> 3;
            int kq = (s & 7) * 4;
            float4 a = *(const float4*)&A[(size_t)(rbase + row) * D_MODEL + k0 + kq];
            As[kq + 0][row] = a.x; As[kq + 1][row] = a.y;
            As[kq + 2][row] = a.z; As[kq + 3][row] = a.w;
            float4 w = *(const float4*)&W[(size_t)(cbase + row) * D_MODEL + k0 + kq];
            Ws[kq + 0][row] = w.x; Ws[kq + 1][row] = w.y;
            Ws[kq + 2][row] = w.z; Ws[kq + 3][row] = w.w;
        }
        __syncthreads();
#pragma unroll
        for (int kk = 0; kk < 32; kk++) {
            float4 a = *(const float4*)&As[kk][ty * 4];
            float4 w = *(const float4*)&Ws[kk][tx * 4];
            acc[0][0] += a.x * w.x; acc[0][1] += a.x * w.y; acc[0][2] += a.x * w.z; acc[0][3] += a.x * w.w;
            acc[1][0] += a.y * w.x; acc[1][1] += a.y * w.y; acc[1][2] += a.y * w.z; acc[1][3] += a.y * w.w;
            acc[2][0] += a.z * w.x; acc[2][1] += a.z * w.y; acc[2][2] += a.z * w.z; acc[2][3] += a.z * w.w;
            acc[3][0] += a.w * w.x; acc[3][1] += a.w * w.y; acc[3][2] += a.w * w.z; acc[3][3] += a.w * w.w;
        }
        __syncthreads();
    }

#pragma unroll
    for (int i = 0; i < 4; i++) {
        int r = rbase + ty * 4 + i;
#pragma unroll
        for (int j = 0; j < 4; j++) {
            int c = cbase + tx * 4 + j;
            float v = acc[i][j] + bias[c];
            if (bhnd) {
                int b = r >> 10, n = r & 1023;
                int h = c >> 5, dk = c & 31;
                out[(size_t)(((b << 3) + h) * N_SEQ + n) * D_HEAD + dk] = v;
            } else {
                out[(size_t)r * D_MODEL + c] = v;
            }
        }
    }
}

// ---------------------------------------------------------------------------
// Fused flash attention with 3 additive biases + key-padding mask.
// grid = (N/64 q-tiles, B*H). block = 256 threads (16x16).
// Per key tile of 64: S = Q K^T * scale + edge + spat + rank + mask,
// online softmax, O += P V. Each bias element is read exactly once.
// ---------------------------------------------------------------------------
__global__ __launch_bounds__(256) void attn_kernel(
    const float* __restrict__ edge,
    const float* __restrict__ spat,
    const float* __restrict__ rnk)
{
    __shared__ float Qs[32][68];   // [k][q] transposed
    __shared__ float Ks[32][68];   // [k][kcol] transposed
    __shared__ float Vs[64][36];   // [kcol][d]
    __shared__ float Ps[64][68];   // [q][kcol]
    __shared__ float msk[64];
    __shared__ float row_m[64], row_l[64], row_scale[64], row_mc[64];

    const int tid = threadIdx.x;
    const int tx = tid & 15;
    const int ty = tid >> 4;
    const int qb = blockIdx.x * 64;
    const int bh = blockIdx.y;          // b*8 + h
    const int b = bh >> 3;
    const int h = bh & 7;

    // Load Q tile once, transposed [k][q]
    const float* Qg = g_Q + (size_t)(bh * N_SEQ + qb) * D_HEAD;
#pragma unroll
    for (int q = 0; q < 2; q++) {
        int s = q * 256 + tid;
        int row = s >> 3;
        int kq = (s & 7) * 4;
        float4 a = *(const float4*)&Qg[row * D_HEAD + kq];
        Qs[kq + 0][row] = a.x; Qs[kq + 1][row] = a.y;
        Qs[kq + 2][row] = a.z; Qs[kq + 3][row] = a.w;
    }
    if (tid < 64) {
        row_m[tid] = __int_as_float(0xff800000);  // -inf
        row_l[tid] = 0.0f;
    }

    float o[4][2];
#pragma unroll
    for (int i = 0; i < 4; i++) { o[i][0] = 0.0f; o[i][1] = 0.0f; }

    const float* maskp = g_maskval + b * N_SEQ;
    const int bias_row0 = (bh * N_SEQ + qb);  // row index into [BH*N, N]

    for (int kb = 0; kb < N_SEQ; kb += 64) {
        __syncthreads();   // protect smem from previous iteration's reads

        // Load K (transposed) and V (direct) tiles + mask slice
        const float* Kg = g_K + (size_t)(bh * N_SEQ + kb) * D_HEAD;
        const float* Vg = g_V + (size_t)(bh * N_SEQ + kb) * D_HEAD;
#pragma unroll
        for (int q = 0; q < 2; q++) {
            int s = q * 256 + tid;
            int row = s >> 3;
            int kq = (s & 7) * 4;
            float4 a = *(const float4*)&Kg[row * D_HEAD + kq];
            Ks[kq + 0][row] = a.x; Ks[kq + 1][row] = a.y;
            Ks[kq + 2][row] = a.z; Ks[kq + 3][row] = a.w;
            float4 v = *(const float4*)&Vg[row * D_HEAD + kq];
            *(float4*)&Vs[row][kq] = v;
        }
        if (tid < 64) msk[tid] = maskp[kb + tid];
        __syncthreads();

        // ---- S = Q K^T ----
        float c[4][4];
#pragma unroll
        for (int i = 0; i < 4; i++)
#pragma unroll
            for (int j = 0; j < 4; j++) c[i][j] = 0.0f;
#pragma unroll
        for (int kk = 0; kk < 32; kk++) {
            float4 a = *(const float4*)&Qs[kk][ty * 4];
            float4 w = *(const float4*)&Ks[kk][tx * 4];
            c[0][0] += a.x * w.x; c[0][1] += a.x * w.y; c[0][2] += a.x * w.z; c[0][3] += a.x * w.w;
            c[1][0] += a.y * w.x; c[1][1] += a.y * w.y; c[1][2] += a.y * w.z; c[1][3] += a.y * w.w;
            c[2][0] += a.z * w.x; c[2][1] += a.z * w.y; c[2][2] += a.z * w.z; c[2][3] += a.z * w.w;
            c[3][0] += a.w * w.x; c[3][1] += a.w * w.y; c[3][2] += a.w * w.z; c[3][3] += a.w * w.w;
        }

        // ---- scale + biases + mask, compute per-thread row maxima ----
        float mk0 = msk[tx * 4 + 0], mk1 = msk[tx * 4 + 1];
        float mk2 = msk[tx * 4 + 2], mk3 = msk[tx * 4 + 3];
        float mloc[4];
#pragma unroll
        for (int i = 0; i < 4; i++) {
            size_t ro = (size_t)(bias_row0 + ty * 4 + i) * N_SEQ + kb + tx * 4;
            float4 e = *(const float4*)(edge + ro);
            float4 s4 = *(const float4*)(spat + ro);
            float4 r4 = *(const float4*)(rnk + ro);
            c[i][0] = fmaf(c[i][0], ATT_SCALE, e.x) + s4.x + r4.x + mk0;
            c[i][1] = fmaf(c[i][1], ATT_SCALE, e.y) + s4.y + r4.y + mk1;
            c[i][2] = fmaf(c[i][2], ATT_SCALE, e.z) + s4.z + r4.z + mk2;
            c[i][3] = fmaf(c[i][3], ATT_SCALE, e.w) + s4.w + r4.w + mk3;
            mloc[i] = fmaxf(fmaxf(c[i][0], c[i][1]), fmaxf(c[i][2], c[i][3]));
        }
        // reduce row max across the 16 tx threads (within half-warp)
#pragma unroll
        for (int i = 0; i < 4; i++) {
#pragma unroll
            for (int off = 8; off > 0; off >>= 1)
                mloc[i] = fmaxf(mloc[i], __shfl_xor_sync(0xffffffffu, mloc[i], off));
        }
        if (tx == 0) {
#pragma unroll
            for (int i = 0; i < 4; i++) {
                int r = ty * 4 + i;
                float mo = row_m[r];
                float mn = fmaxf(mo, mloc[i]);
                row_m[r] = mn;
                float moc = fmaxf(mo, -1e30f);
                float mnc = fmaxf(mn, -1e30f);
                float sc = __expf(moc - mnc);
                row_l[r] *= sc;
                row_scale[r] = sc;
                row_mc[r] = mnc;
            }
        }
        __syncthreads();

        // ---- P = exp(S - m), row sums, write P to smem ----
        float rs[4];
#pragma unroll
        for (int i = 0; i < 4; i++) {
            float mc = row_mc[ty * 4 + i];
            float p0 = __expf(c[i][0] - mc);
            float p1 = __expf(c[i][1] - mc);
            float p2 = __expf(c[i][2] - mc);
            float p3 = __expf(c[i][3] - mc);
            *(float4*)&Ps[ty * 4 + i][tx * 4] = make_float4(p0, p1, p2, p3);
            rs[i] = (p0 + p1) + (p2 + p3);
        }
#pragma unroll
        for (int i = 0; i < 4; i++) {
#pragma unroll
            for (int off = 8; off > 0; off >>= 1)
                rs[i] += __shfl_xor_sync(0xffffffffu, rs[i], off);
        }
        if (tx == 0) {
#pragma unroll
            for (int i = 0; i < 4; i++) row_l[ty * 4 + i] += rs[i];
        }
        __syncthreads();

        // ---- O = O * scale + P V ----
#pragma unroll
        for (int i = 0; i < 4; i++) {
            float sc = row_scale[ty * 4 + i];
            o[i][0] *= sc;
            o[i][1] *= sc;
        }
#pragma unroll
        for (int k4 = 0; k4 < 64; k4 += 4) {
            float2 v0 = *(const float2*)&Vs[k4 + 0][tx * 2];
            float2 v1 = *(const float2*)&Vs[k4 + 1][tx * 2];
            float2 v2 = *(const float2*)&Vs[k4 + 2][tx * 2];
            float2 v3 = *(const float2*)&Vs[k4 + 3][tx * 2];
#pragma unroll
            for (int i = 0; i < 4; i++) {
                float4 p = *(const float4*)&Ps[ty * 4 + i][k4];
                o[i][0] += p.x * v0.x + p.y * v1.x + p.z * v2.x + p.w * v3.x;
                o[i][1] += p.x * v0.y + p.y * v1.y + p.z * v2.y + p.w * v3.y;
            }
        }
    }

    // Normalize and scatter to [b, n, h*32 + d]
#pragma unroll
    for (int i = 0; i < 4; i++) {
        int r = ty * 4 + i;
        float l = row_l[r];
        float inv = (l > 0.0f) ? (1.0f / l) : 0.0f;   // nan_to_num: all-masked row -> 0
        int n = qb + r;
        float* dst = g_AO + (size_t)(b * N_SEQ + n) * D_MODEL + h * D_HEAD + tx * 2;
        dst[0] = o[i][0] * inv;
        dst[1] = o[i][1] * inv;
    }
}

// ---------------------------------------------------------------------------
extern "C" void kernel_launch(void* const* d_in, const int* in_sizes, int n_in,
                              void* d_out, int out_size)
{
    const float* x    = (const float*)d_in[0];
    const float* edge = (const float*)d_in[1];
    const float* spat = (const float*)d_in[2];
    const float* rnk  = (const float*)d_in[3];
    const void*  mask = d_in[4];
    const float* Wq = (const float*)d_in[5];
    const float* bq = (const float*)d_in[6];
    const float* Wk = (const float*)d_in[7];
    const float* bk = (const float*)d_in[8];
    const float* Wv = (const float*)d_in[9];
    const float* bv = (const float*)d_in[10];
    const float* Wo = (const float*)d_in[11];
    const float* bo = (const float*)d_in[12];

    float *gQ, *gK, *gV, *gAO;
    cudaGetSymbolAddress((void**)&gQ,  g_Q);
    cudaGetSymbolAddress((void**)&gK,  g_K);
    cudaGetSymbolAddress((void**)&gV,  g_V);
    cudaGetSymbolAddress((void**)&gAO, g_AO);

    prep_mask_kernel<<<1, 256>>>(mask);

    dim3 gg(64, 4);   // 4096/64 row tiles, 256/64 col tiles
    gemm_proj_kernel<<<gg, 256>>>(x, Wq, bq, gQ, 1);
    gemm_proj_kernel<<<gg, 256>>>(x, Wk, bk, gK, 1);
    gemm_proj_kernel<<<gg, 256>>>(x, Wv, bv, gV, 1);

    attn_kernel<<<dim3(16, 32), 256>>>(edge, spat, rnk);

    gemm_proj_kernel<<<gg, 256>>>(gAO, Wo, bo, (float*)d_out, 0);
}

// round 3
// speedup vs baseline: 1.5270x; 1.5270x over previous
#include <cuda_runtime.h>
#include <math.h>

#define BATCH   4
#define N_SEQ   1024
#define D_MODEL 256
#define N_HEADS 8
#define D_HEAD  32
#define ATT_SCALE 0.17677669529663687f   // 1/sqrt(32)

// Scratch (device globals: no allocation allowed in kernel_launch)
__device__ float g_Q[BATCH * N_HEADS * N_SEQ * D_HEAD];   // [b,h,n,dk]  (tf32-rounded)
__device__ float g_K[BATCH * N_HEADS * N_SEQ * D_HEAD];   // (tf32-rounded)
__device__ float g_V[BATCH * N_HEADS * N_SEQ * D_HEAD];   // (tf32-rounded)
__device__ float g_AO[BATCH * N_SEQ * D_MODEL];           // attention out, [b,n,d]
__device__ float g_maskval[BATCH * N_SEQ];                // 0 or -inf per key

__device__ __forceinline__ unsigned f2tf32(float f) {
    unsigned u;
    asm("cvt.rna.tf32.f32 %0, %1;" : "=r"(u) : "f"(f));
    return u;
}

#define MMA_TF32(d, a, b)                                                     \
    asm volatile(                                                             \
        "mma.sync.aligned.m16n8k8.row.col.f32.tf32.tf32.f32 "                 \
        "{%0,%1,%2,%3}, {%4,%5,%6,%7}, {%8,%9}, {%0,%1,%2,%3};\n"             \
        : "+f"((d)[0]), "+f"((d)[1]), "+f"((d)[2]), "+f"((d)[3])              \
        : "r"((a)[0]), "r"((a)[1]), "r"((a)[2]), "r"((a)[3]),                 \
          "r"((b)[0]), "r"((b)[1]))

// ---------------------------------------------------------------------------
// Mask prep: detect storage dtype of the bool mask (int32 / float32 / uint8)
// ---------------------------------------------------------------------------
__global__ void prep_mask_kernel(const void* __restrict__ mraw) {
    __shared__ int s_mode;
    if (threadIdx.x == 0) {
        const unsigned int* mi = (const unsigned int*)mraw;
        int ok_int = 1, ok_float = 1;
        for (int i = 0; i < 1024; i++) {
            unsigned int v = mi[i];
            if (v > 1u) ok_int = 0;
            if (v != 0u && v != 0x3F800000u) ok_float = 0;
        }
        s_mode = ok_int ? 0 : (ok_float ? 1 : 2);
    }
    __syncthreads();
    const int mode = s_mode;
    const float NEG_INF = __int_as_float(0xff800000);
    for (int i = threadIdx.x; i < BATCH * N_SEQ; i += blockDim.x) {
        int masked;
        if (mode == 0)      masked = ((const int*)mraw)[i] != 0;
        else if (mode == 1) masked = ((const unsigned int*)mraw)[i] != 0u;
        else                masked = ((const unsigned char*)mraw)[i] != 0;
        g_maskval[i] = masked ? NEG_INF : 0.0f;
    }
}

// ---------------------------------------------------------------------------
// Fused QKV projection: one launch, gridDim.z selects Q/K/V.
// C[r,c] = sum_k A[r,k]*W[c,k] + bias[c]; output scattered to [b,h,n,dk],
// tf32-rounded for the tensor-core attention that consumes it.
// ---------------------------------------------------------------------------
__global__ __launch_bounds__(256) void gemm_qkv_kernel(
    const float* __restrict__ A,
    const float* __restrict__ Wq, const float* __restrict__ Wk, const float* __restrict__ Wv,
    const float* __restrict__ bq, const float* __restrict__ bk, const float* __restrict__ bv)
{
    const int z = blockIdx.z;
    const float* W    = (z == 0) ? Wq : (z == 1) ? Wk : Wv;
    const float* bias = (z == 0) ? bq : (z == 1) ? bk : bv;
    float* out        = (z == 0) ? g_Q : (z == 1) ? g_K : g_V;

    __shared__ float As[32][68];
    __shared__ float Ws[32][68];

    const int tid = threadIdx.x;
    const int tx = tid & 15;
    const int ty = tid >> 4;
    const int rbase = blockIdx.x * 64;
    const int cbase = blockIdx.y * 64;

    float acc[4][4];
#pragma unroll
    for (int i = 0; i < 4; i++)
#pragma unroll
        for (int j = 0; j < 4; j++) acc[i][j] = 0.0f;

    for (int k0 = 0; k0 < D_MODEL; k0 += 32) {
#pragma unroll
        for (int q = 0; q < 2; q++) {
            int s = q * 256 + tid;
            int row = s >> 3;
            int kq = (s & 7) * 4;
            float4 a = *(const float4*)&A[(size_t)(rbase + row) * D_MODEL + k0 + kq];
            As[kq + 0][row] = a.x; As[kq + 1][row] = a.y;
            As[kq + 2][row] = a.z; As[kq + 3][row] = a.w;
            float4 w = *(const float4*)&W[(size_t)(cbase + row) * D_MODEL + k0 + kq];
            Ws[kq + 0][row] = w.x; Ws[kq + 1][row] = w.y;
            Ws[kq + 2][row] = w.z; Ws[kq + 3][row] = w.w;
        }
        __syncthreads();
#pragma unroll
        for (int kk = 0; kk < 32; kk++) {
            float4 a = *(const float4*)&As[kk][ty * 4];
            float4 w = *(const float4*)&Ws[kk][tx * 4];
            acc[0][0] += a.x * w.x; acc[0][1] += a.x * w.y; acc[0][2] += a.x * w.z; acc[0][3] += a.x * w.w;
            acc[1][0] += a.y * w.x; acc[1][1] += a.y * w.y; acc[1][2] += a.y * w.z; acc[1][3] += a.y * w.w;
            acc[2][0] += a.z * w.x; acc[2][1] += a.z * w.y; acc[2][2] += a.z * w.z; acc[2][3] += a.z * w.w;
            acc[3][0] += a.w * w.x; acc[3][1] += a.w * w.y; acc[3][2] += a.w * w.z; acc[3][3] += a.w * w.w;
        }
        __syncthreads();
    }

#pragma unroll
    for (int i = 0; i < 4; i++) {
        int r = rbase + ty * 4 + i;
#pragma unroll
        for (int j = 0; j < 4; j++) {
            int c = cbase + tx * 4 + j;
            float v = acc[i][j] + bias[c];
            v = __uint_as_float(f2tf32(v));           // round to tf32 for mma consumers
            int b = r >> 10, n = r & 1023;
            int h = c >> 5, dk = c & 31;
            out[(size_t)(((b << 3) + h) * N_SEQ + n) * D_HEAD + dk] = v;
        }
    }
}

// ---------------------------------------------------------------------------
// Output projection (plain fp32, writes d_out [4096,256])
// ---------------------------------------------------------------------------
__global__ __launch_bounds__(256) void gemm_o_kernel(
    const float* __restrict__ A, const float* __restrict__ W,
    const float* __restrict__ bias, float* __restrict__ out)
{
    __shared__ float As[32][68];
    __shared__ float Ws[32][68];

    const int tid = threadIdx.x;
    const int tx = tid & 15;
    const int ty = tid >> 4;
    const int rbase = blockIdx.x * 64;
    const int cbase = blockIdx.y * 64;

    float acc[4][4];
#pragma unroll
    for (int i = 0; i < 4; i++)
#pragma unroll
        for (int j = 0; j < 4; j++) acc[i][j] = 0.0f;

    for (int k0 = 0; k0 < D_MODEL; k0 += 32) {
#pragma unroll
        for (int q = 0; q < 2; q++) {
            int s = q * 256 + tid;
            int row = s >> 3;
            int kq = (s & 7) * 4;
            float4 a = *(const float4*)&A[(size_t)(rbase + row) * D_MODEL + k0 + kq];
            As[kq + 0][row] = a.x; As[kq + 1][row] = a.y;
            As[kq + 2][row] = a.z; As[kq + 3][row] = a.w;
            float4 w = *(const float4*)&W[(size_t)(cbase + row) * D_MODEL + k0 + kq];
            Ws[kq + 0][row] = w.x; Ws[kq + 1][row] = w.y;
            Ws[kq + 2][row] = w.z; Ws[kq + 3][row] = w.w;
        }
        __syncthreads();
#pragma unroll
        for (int kk = 0; kk < 32; kk++) {
            float4 a = *(const float4*)&As[kk][ty * 4];
            float4 w = *(const float4*)&Ws[kk][tx * 4];
            acc[0][0] += a.x * w.x; acc[0][1] += a.x * w.y; acc[0][2] += a.x * w.z; acc[0][3] += a.x * w.w;
            acc[1][0] += a.y * w.x; acc[1][1] += a.y * w.y; acc[1][2] += a.y * w.z; acc[1][3] += a.y * w.w;
            acc[2][0] += a.z * w.x; acc[2][1] += a.z * w.y; acc[2][2] += a.z * w.z; acc[2][3] += a.z * w.w;
            acc[3][0] += a.w * w.x; acc[3][1] += a.w * w.y; acc[3][2] += a.w * w.z; acc[3][3] += a.w * w.w;
        }
        __syncthreads();
    }

#pragma unroll
    for (int i = 0; i < 4; i++) {
        int r = rbase + ty * 4 + i;
#pragma unroll
        for (int j = 0; j < 4; j++) {
            int c = cbase + tx * 4 + j;
            out[(size_t)r * D_MODEL + c] = acc[i][j] + bias[c];
        }
    }
}

// ---------------------------------------------------------------------------
// Tensor-core flash attention with 3 additive biases + key-padding mask.
// grid=(16, 32), block=128 (4 warps). Warp w owns q rows [w*16, w*16+16).
// ---------------------------------------------------------------------------
__global__ __launch_bounds__(128) void attn_tc_kernel(
    const float* __restrict__ edge,
    const float* __restrict__ spat,
    const float* __restrict__ rnk)
{
    __shared__ float Qs[64][36];
    __shared__ float Ks[64][36];
    __shared__ float Vs[64][40];
    __shared__ float Ps[64][68];    // FIXED: full 64 columns + pad (was [64][36] — OOB)

    const int tid  = threadIdx.x;
    const int lane = tid & 31;
    const int w    = tid >> 5;       // warp id 0..3
    const int g    = lane >> 2;      // group row 0..7
    const int t    = lane & 3;       // thread-in-group 0..3
    const int qb   = blockIdx.x * 64;
    const int bh   = blockIdx.y;     // b*8 + h
    const int b    = bh >> 3;
    const int h    = bh & 7;
    const int w16  = w * 16;

    // ---- Load Q tile (coalesced), extract A fragments to registers ----
    const float* Qg = g_Q + ((size_t)bh * N_SEQ + qb) * D_HEAD;
#pragma unroll
    for (int it = 0; it < 4; it++) {
        int s = it * 128 + tid;
        int row = s >> 3;
        int kq = (s & 7) * 4;
        float4 a = *(const float4*)&Qg[row * D_HEAD + kq];
        Qs[row][kq + 0] = a.x; Qs[row][kq + 1] = a.y;
        Qs[row][kq + 2] = a.z; Qs[row][kq + 3] = a.w;
    }
    __syncthreads();

    unsigned qa[4][4];
#pragma unroll
    for (int kk = 0; kk < 4; kk++) {
        qa[kk][0] = __float_as_uint(Qs[w16 + g    ][kk * 8 + t    ]);
        qa[kk][1] = __float_as_uint(Qs[w16 + g + 8][kk * 8 + t    ]);
        qa[kk][2] = __float_as_uint(Qs[w16 + g    ][kk * 8 + t + 4]);
        qa[kk][3] = __float_as_uint(Qs[w16 + g + 8][kk * 8 + t + 4]);
    }

    float o[4][4];
#pragma unroll
    for (int n = 0; n < 4; n++)
#pragma unroll
        for (int j = 0; j < 4; j++) o[n][j] = 0.0f;

    float m0 = __int_as_float(0xff800000), m1 = m0;   // running row maxima
    float l0 = 0.0f, l1 = 0.0f;                        // running row sums

    const float* maskp = g_maskval + b * N_SEQ;
    const size_t brow0 = ((size_t)bh * N_SEQ + qb + w16 + g) * N_SEQ;   // bias row (g)
    const size_t brow1 = brow0 + (size_t)8 * N_SEQ;                     // bias row (g+8)

    for (int kb = 0; kb < N_SEQ; kb += 64) {
        __syncthreads();   // all warps done with Ks/Vs of previous tile

        const float* Kg = g_K + ((size_t)bh * N_SEQ + kb) * D_HEAD;
        const float* Vg = g_V + ((size_t)bh * N_SEQ + kb) * D_HEAD;
#pragma unroll
        for (int it = 0; it < 4; it++) {
            int s = it * 128 + tid;
            int row = s >> 3;
            int kq = (s & 7) * 4;
            float4 a = *(const float4*)&Kg[row * D_HEAD + kq];
            Ks[row][kq + 0] = a.x; Ks[row][kq + 1] = a.y;
            Ks[row][kq + 2] = a.z; Ks[row][kq + 3] = a.w;
            float4 v = *(const float4*)&Vg[row * D_HEAD + kq];
            Vs[row][kq + 0] = v.x; Vs[row][kq + 1] = v.y;
            Vs[row][kq + 2] = v.z; Vs[row][kq + 3] = v.w;
        }
        __syncthreads();

        // ---- S = Q K^T  (8 n-chunks x 4 k-chunks of m16n8k8) ----
        float sc[8][4];
#pragma unroll
        for (int n8 = 0; n8 < 8; n8++) {
            sc[n8][0] = sc[n8][1] = sc[n8][2] = sc[n8][3] = 0.0f;
#pragma unroll
            for (int kk = 0; kk < 4; kk++) {
                unsigned bb[2];
                bb[0] = __float_as_uint(Ks[n8 * 8 + g][kk * 8 + t    ]);
                bb[1] = __float_as_uint(Ks[n8 * 8 + g][kk * 8 + t + 4]);
                MMA_TF32(sc[n8], qa[kk], bb);
            }
        }

        // ---- scale + biases + mask ----
#pragma unroll
        for (int n8 = 0; n8 < 8; n8++) {
            const size_t co = (size_t)(kb + n8 * 8 + 2 * t);
            float2 mk = *(const float2*)&maskp[co];
            float2 e0 = *(const float2*)&edge[brow0 + co];
            float2 s0 = *(const float2*)&spat[brow0 + co];
            float2 r0 = *(const float2*)&rnk [brow0 + co];
            float2 e1 = *(const float2*)&edge[brow1 + co];
            float2 s1 = *(const float2*)&spat[brow1 + co];
            float2 r1 = *(const float2*)&rnk [brow1 + co];
            sc[n8][0] = fmaf(sc[n8][0], ATT_SCALE, e0.x + s0.x) + (r0.x + mk.x);
            sc[n8][1] = fmaf(sc[n8][1], ATT_SCALE, e0.y + s0.y) + (r0.y + mk.y);
            sc[n8][2] = fmaf(sc[n8][2], ATT_SCALE, e1.x + s1.x) + (r1.x + mk.x);
            sc[n8][3] = fmaf(sc[n8][3], ATT_SCALE, e1.y + s1.y) + (r1.y + mk.y);
        }

        // ---- row maxima (rows g and g+8) ----
        float ml0 = sc[0][0], ml1 = sc[0][2];
#pragma unroll
        for (int n8 = 0; n8 < 8; n8++) {
            ml0 = fmaxf(ml0, fmaxf(sc[n8][0], sc[n8][1]));
            ml1 = fmaxf(ml1, fmaxf(sc[n8][2], sc[n8][3]));
        }
        ml0 = fmaxf(ml0, __shfl_xor_sync(0xffffffffu, ml0, 1));
        ml0 = fmaxf(ml0, __shfl_xor_sync(0xffffffffu, ml0, 2));
        ml1 = fmaxf(ml1, __shfl_xor_sync(0xffffffffu, ml1, 1));
        ml1 = fmaxf(ml1, __shfl_xor_sync(0xffffffffu, ml1, 2));

        float mn0 = fmaxf(m0, ml0);
        float mn1 = fmaxf(m1, ml1);
        float mc0 = fmaxf(mn0, -1e30f);
        float mc1 = fmaxf(mn1, -1e30f);
        float rs0 = __expf(fmaxf(m0, -1e30f) - mc0);
        float rs1 = __expf(fmaxf(m1, -1e30f) - mc1);
        m0 = mn0; m1 = mn1;

        // ---- P = exp(S - m), write to Ps (per-warp rows), local row sums ----
        float sum0 = 0.0f, sum1 = 0.0f;
#pragma unroll
        for (int n8 = 0; n8 < 8; n8++) {
            float p0 = __expf(sc[n8][0] - mc0);
            float p1 = __expf(sc[n8][1] - mc0);
            float p2 = __expf(sc[n8][2] - mc1);
            float p3 = __expf(sc[n8][3] - mc1);
            sum0 += p0 + p1;
            sum1 += p2 + p3;
            float2 w0, w1;
            w0.x = __uint_as_float(f2tf32(p0)); w0.y = __uint_as_float(f2tf32(p1));
            w1.x = __uint_as_float(f2tf32(p2)); w1.y = __uint_as_float(f2tf32(p3));
            *(float2*)&Ps[w16 + g    ][n8 * 8 + 2 * t] = w0;
            *(float2*)&Ps[w16 + g + 8][n8 * 8 + 2 * t] = w1;
        }
        sum0 += __shfl_xor_sync(0xffffffffu, sum0, 1);
        sum0 += __shfl_xor_sync(0xffffffffu, sum0, 2);
        sum1 += __shfl_xor_sync(0xffffffffu, sum1, 1);
        sum1 += __shfl_xor_sync(0xffffffffu, sum1, 2);
        l0 = l0 * rs0 + sum0;
        l1 = l1 * rs1 + sum1;

        // ---- rescale O ----
#pragma unroll
        for (int n = 0; n < 4; n++) {
            o[n][0] *= rs0; o[n][1] *= rs0;
            o[n][2] *= rs1; o[n][3] *= rs1;
        }

        __syncwarp();   // Ps rows for this warp visible warp-wide

        // ---- O += P V  (8 k-chunks x 4 d-chunks of m16n8k8) ----
#pragma unroll
        for (int kk = 0; kk < 8; kk++) {
            unsigned pa[4];
            pa[0] = __float_as_uint(Ps[w16 + g    ][kk * 8 + t    ]);
            pa[1] = __float_as_uint(Ps[w16 + g + 8][kk * 8 + t    ]);
            pa[2] = __float_as_uint(Ps[w16 + g    ][kk * 8 + t + 4]);
            pa[3] = __float_as_uint(Ps[w16 + g + 8][kk * 8 + t + 4]);
#pragma unroll
            for (int n = 0; n < 4; n++) {
                unsigned bb[2];
                bb[0] = __float_as_uint(Vs[kk * 8 + t    ][n * 8 + g]);
                bb[1] = __float_as_uint(Vs[kk * 8 + t + 4][n * 8 + g]);
                MMA_TF32(o[n], pa, bb);
            }
        }
    }

    // ---- normalize + scatter to [b, n, h*32 + d] ----
    float inv0 = (l0 > 0.0f) ? (1.0f / l0) : 0.0f;
    float inv1 = (l1 > 0.0f) ? (1.0f / l1) : 0.0f;
    const int r0 = qb + w16 + g;
    const int r1 = r0 + 8;
#pragma unroll
    for (int n = 0; n < 4; n++) {
        int d = n * 8 + 2 * t;
        float* dst0 = g_AO + ((size_t)(b * N_SEQ + r0)) * D_MODEL + h * D_HEAD + d;
        float* dst1 = g_AO + ((size_t)(b * N_SEQ + r1)) * D_MODEL + h * D_HEAD + d;
        dst0[0] = o[n][0] * inv0; dst0[1] = o[n][1] * inv0;
        dst1[0] = o[n][2] * inv1; dst1[1] = o[n][3] * inv1;
    }
}

// ---------------------------------------------------------------------------
extern "C" void kernel_launch(void* const* d_in, const int* in_sizes, int n_in,
                              void* d_out, int out_size)
{
    const float* x    = (const float*)d_in[0];
    const float* edge = (const float*)d_in[1];
    const float* spat = (const float*)d_in[2];
    const float* rnk  = (const float*)d_in[3];
    const void*  mask = d_in[4];
    const float* Wq = (const float*)d_in[5];
    const float* bq = (const float*)d_in[6];
    const float* Wk = (const float*)d_in[7];
    const float* bk = (const float*)d_in[8];
    const float* Wv = (const float*)d_in[9];
    const float* bv = (const float*)d_in[10];
    const float* Wo = (const float*)d_in[11];
    const float* bo = (const float*)d_in[12];

    float* gAO;
    cudaGetSymbolAddress((void**)&gAO, g_AO);

    prep_mask_kernel<<<1, 256>>>(mask);

    dim3 gq(64, 4, 3);   // fused Q/K/V: 768 CTAs in one launch
    gemm_qkv_kernel<<<gq, 256>>>(x, Wq, Wk, Wv, bq, bk, bv);

    attn_tc_kernel<<<dim3(16, 32), 128>>>(edge, spat, rnk);

    gemm_o_kernel<<<dim3(64, 4), 256>>>(gAO, Wo, bo, (float*)d_out);
}

// round 4
// speedup vs baseline: 2.2273x; 1.4586x over previous
#include <cuda_runtime.h>
#include <math.h>

#define BATCH   4
#define N_SEQ   1024
#define D_MODEL 256
#define N_HEADS 8
#define D_HEAD  32
#define ATT_SCALE 0.17677669529663687f   // 1/sqrt(32)

// Scratch (device globals: no allocation allowed in kernel_launch)
__device__ float g_Q[BATCH * N_HEADS * N_SEQ * D_HEAD];   // [b,h,n,dk]  tf32, pre-scaled
__device__ float g_K[BATCH * N_HEADS * N_SEQ * D_HEAD];   // tf32-rounded
__device__ float g_V[BATCH * N_HEADS * N_SEQ * D_HEAD];   // tf32-rounded
__device__ float g_AO[BATCH * N_SEQ * D_MODEL];           // attention out, tf32-rounded
__device__ float g_maskval[BATCH * N_SEQ];                // 0 or -inf per key

__device__ __forceinline__ unsigned f2tf32(float f) {
    unsigned u;
    asm("cvt.rna.tf32.f32 %0, %1;" : "=r"(u) : "f"(f));
    return u;
}

#define MMA_TF32(d, a, b)                                                     \
    asm volatile(                                                             \
        "mma.sync.aligned.m16n8k8.row.col.f32.tf32.tf32.f32 "                 \
        "{%0,%1,%2,%3}, {%4,%5,%6,%7}, {%8,%9}, {%0,%1,%2,%3};\n"             \
        : "+f"((d)[0]), "+f"((d)[1]), "+f"((d)[2]), "+f"((d)[3])              \
        : "r"((a)[0]), "r"((a)[1]), "r"((a)[2]), "r"((a)[3]),                 \
          "r"((b)[0]), "r"((b)[1]))

__device__ __forceinline__ void cp_async16(void* s, const void* g) {
    unsigned sa = (unsigned)__cvta_generic_to_shared(s);
    asm volatile("cp.async.cg.shared.global [%0], [%1], 16;" :: "r"(sa), "l"(g));
}
#define CP_COMMIT() asm volatile("cp.async.commit_group;")
#define CP_WAIT0()  asm volatile("cp.async.wait_group 0;")

// ---------------------------------------------------------------------------
// Mask prep (parallel): detect storage dtype (int32 / float32 / uint8),
// expand to float additive mask (0 or -inf).
// ---------------------------------------------------------------------------
__global__ void prep_mask_kernel(const void* __restrict__ mraw) {
    const int tid = threadIdx.x;   // 256
    const unsigned* mi = (const unsigned*)mraw;
    int ok_int = 1, ok_float = 1;
    for (int i = tid; i < 1024; i += 256) {
        unsigned v = mi[i];
        if (v > 1u) ok_int = 0;
        if (v != 0u && v != 0x3F800000u) ok_float = 0;
    }
    int all_int   = __syncthreads_and(ok_int);
    int all_float = __syncthreads_and(ok_float);
    const int mode = all_int ? 0 : (all_float ? 1 : 2);
    const float NEG_INF = __int_as_float(0xff800000);
    for (int i = tid; i < BATCH * N_SEQ; i += 256) {
        int masked;
        if (mode == 0)      masked = ((const int*)mraw)[i] != 0;
        else if (mode == 1) masked = ((const unsigned*)mraw)[i] != 0u;
        else                masked = ((const unsigned char*)mraw)[i] != 0;
        g_maskval[i] = masked ? NEG_INF : 0.0f;
    }
}

// ---------------------------------------------------------------------------
// Fused QKV projection, tf32 tensor cores. grid=(64,4,3), block=128 (4 warps).
// C[r,c] = sum_k x[r,k]*W[c,k] + bias[c]; Q additionally scaled by ATT_SCALE.
// Output tf32-rounded, scattered to [b,h,n,dk].
// ---------------------------------------------------------------------------
__global__ __launch_bounds__(128) void gemm_qkv_tc(
    const float* __restrict__ x,
    const float* __restrict__ Wq, const float* __restrict__ Wk, const float* __restrict__ Wv,
    const float* __restrict__ bq, const float* __restrict__ bk, const float* __restrict__ bv)
{
    __shared__ float As[64][68];
    __shared__ float Ws[64][68];

    const int z = blockIdx.z;
    const float* W    = (z == 0) ? Wq : (z == 1) ? Wk : Wv;
    const float* bias = (z == 0) ? bq : (z == 1) ? bk : bv;
    float* out        = (z == 0) ? g_Q : (z == 1) ? g_K : g_V;

    const int tid  = threadIdx.x;
    const int lane = tid & 31;
    const int w    = tid >> 5;
    const int g    = lane >> 2;
    const int t    = lane & 3;
    const int w16  = w * 16;
    const int rbase = blockIdx.x * 64;
    const int cbase = blockIdx.y * 64;

    float sc[8][4];
#pragma unroll
    for (int n = 0; n < 8; n++)
#pragma unroll
        for (int j = 0; j < 4; j++) sc[n][j] = 0.0f;

    for (int k0 = 0; k0 < D_MODEL; k0 += 64) {
        __syncthreads();
#pragma unroll
        for (int it = 0; it < 8; it++) {
            int s = it * 128 + tid;
            int row = s >> 4;
            int c16 = (s & 15) * 4;
            cp_async16(&As[row][c16], &x[(size_t)(rbase + row) * D_MODEL + k0 + c16]);
        }
#pragma unroll
        for (int it = 0; it < 8; it++) {
            int s = it * 128 + tid;
            int row = s >> 4;
            int c16 = (s & 15) * 4;
            cp_async16(&Ws[row][c16], &W[(size_t)(cbase + row) * D_MODEL + k0 + c16]);
        }
        CP_COMMIT();
        CP_WAIT0();
        __syncthreads();

        unsigned qa[8][4];
#pragma unroll
        for (int kk = 0; kk < 8; kk++) {
            qa[kk][0] = f2tf32(As[w16 + g    ][kk * 8 + t    ]);
            qa[kk][1] = f2tf32(As[w16 + g + 8][kk * 8 + t    ]);
            qa[kk][2] = f2tf32(As[w16 + g    ][kk * 8 + t + 4]);
            qa[kk][3] = f2tf32(As[w16 + g + 8][kk * 8 + t + 4]);
        }
#pragma unroll
        for (int n8 = 0; n8 < 8; n8++) {
#pragma unroll
            for (int kk = 0; kk < 8; kk++) {
                unsigned bb[2];
                bb[0] = f2tf32(Ws[n8 * 8 + g][kk * 8 + t    ]);
                bb[1] = f2tf32(Ws[n8 * 8 + g][kk * 8 + t + 4]);
                MMA_TF32(sc[n8], qa[kk], bb);
            }
        }
    }

    const float scale = (z == 0) ? ATT_SCALE : 1.0f;
#pragma unroll
    for (int n8 = 0; n8 < 8; n8++) {
        int c0 = cbase + n8 * 8 + 2 * t;
        float b0v = bias[c0], b1v = bias[c0 + 1];
        int r0 = rbase + w16 + g;
        int r1 = r0 + 8;
        float2 v0, v1;
        v0.x = __uint_as_float(f2tf32((sc[n8][0] + b0v) * scale));
        v0.y = __uint_as_float(f2tf32((sc[n8][1] + b1v) * scale));
        v1.x = __uint_as_float(f2tf32((sc[n8][2] + b0v) * scale));
        v1.y = __uint_as_float(f2tf32((sc[n8][3] + b1v) * scale));
        int h = c0 >> 5, dk = c0 & 31;
        int b0i = r0 >> 10, n0 = r0 & 1023;
        int b1i = r1 >> 10, n1 = r1 & 1023;
        *(float2*)&out[(size_t)(((b0i << 3) + h) * N_SEQ + n0) * D_HEAD + dk] = v0;
        *(float2*)&out[(size_t)(((b1i << 3) + h) * N_SEQ + n1) * D_HEAD + dk] = v1;
    }
}

// ---------------------------------------------------------------------------
// Output projection, tf32 tensor cores. grid=(64,4), block=128.
// A = g_AO (already tf32-rounded). out[r,c] = sum_k A[r,k]*W[c,k] + bias[c].
// ---------------------------------------------------------------------------
__global__ __launch_bounds__(128) void gemm_o_tc(
    const float* __restrict__ W, const float* __restrict__ bias,
    float* __restrict__ out)
{
    __shared__ float As[64][68];
    __shared__ float Ws[64][68];

    const int tid  = threadIdx.x;
    const int lane = tid & 31;
    const int w    = tid >> 5;
    const int g    = lane >> 2;
    const int t    = lane & 3;
    const int w16  = w * 16;
    const int rbase = blockIdx.x * 64;
    const int cbase = blockIdx.y * 64;

    float sc[8][4];
#pragma unroll
    for (int n = 0; n < 8; n++)
#pragma unroll
        for (int j = 0; j < 4; j++) sc[n][j] = 0.0f;

    for (int k0 = 0; k0 < D_MODEL; k0 += 64) {
        __syncthreads();
#pragma unroll
        for (int it = 0; it < 8; it++) {
            int s = it * 128 + tid;
            int row = s >> 4;
            int c16 = (s & 15) * 4;
            cp_async16(&As[row][c16], &g_AO[(size_t)(rbase + row) * D_MODEL + k0 + c16]);
        }
#pragma unroll
        for (int it = 0; it < 8; it++) {
            int s = it * 128 + tid;
            int row = s >> 4;
            int c16 = (s & 15) * 4;
            cp_async16(&Ws[row][c16], &W[(size_t)(cbase + row) * D_MODEL + k0 + c16]);
        }
        CP_COMMIT();
        CP_WAIT0();
        __syncthreads();

        unsigned qa[8][4];
#pragma unroll
        for (int kk = 0; kk < 8; kk++) {
            qa[kk][0] = __float_as_uint(As[w16 + g    ][kk * 8 + t    ]);
            qa[kk][1] = __float_as_uint(As[w16 + g + 8][kk * 8 + t    ]);
            qa[kk][2] = __float_as_uint(As[w16 + g    ][kk * 8 + t + 4]);
            qa[kk][3] = __float_as_uint(As[w16 + g + 8][kk * 8 + t + 4]);
        }
#pragma unroll
        for (int n8 = 0; n8 < 8; n8++) {
#pragma unroll
            for (int kk = 0; kk < 8; kk++) {
                unsigned bb[2];
                bb[0] = f2tf32(Ws[n8 * 8 + g][kk * 8 + t    ]);
                bb[1] = f2tf32(Ws[n8 * 8 + g][kk * 8 + t + 4]);
                MMA_TF32(sc[n8], qa[kk], bb);
            }
        }
    }

#pragma unroll
    for (int n8 = 0; n8 < 8; n8++) {
        int c0 = cbase + n8 * 8 + 2 * t;
        float b0v = bias[c0], b1v = bias[c0 + 1];
        int r0 = rbase + w16 + g;
        int r1 = r0 + 8;
        float2 v0, v1;
        v0.x = sc[n8][0] + b0v;  v0.y = sc[n8][1] + b1v;
        v1.x = sc[n8][2] + b0v;  v1.y = sc[n8][3] + b1v;
        *(float2*)&out[(size_t)r0 * D_MODEL + c0] = v0;
        *(float2*)&out[(size_t)r1 * D_MODEL + c0] = v1;
    }
}

// ---------------------------------------------------------------------------
// Tensor-core flash attention. grid=(16,32), block=128 (4 warps).
// Q pre-scaled by ATT_SCALE. Per k-tile: cp.async K/V, prefetch biases into
// registers, S-mma overlapping the bias loads, sc += bias, online softmax,
// PV-mma. Each bias element touched exactly once.
// ---------------------------------------------------------------------------
__global__ __launch_bounds__(128) void attn_tc_kernel(
    const float* __restrict__ edge,
    const float* __restrict__ spat,
    const float* __restrict__ rnk)
{
    __shared__ float Ks[64][36];
    __shared__ float Vs[64][40];
    __shared__ float Ps[64][68];   // also used to stage Q in the prologue

    const int tid  = threadIdx.x;
    const int lane = tid & 31;
    const int w    = tid >> 5;
    const int g    = lane >> 2;
    const int t    = lane & 3;
    const int qb   = blockIdx.x * 64;
    const int bh   = blockIdx.y;
    const int b    = bh >> 3;
    const int h    = bh & 7;
    const int w16  = w * 16;

    // ---- Prologue: stage Q tile via cp.async, extract A fragments ----
    const float* Qg = g_Q + ((size_t)bh * N_SEQ + qb) * D_HEAD;
#pragma unroll
    for (int it = 0; it < 4; it++) {
        int s = it * 128 + tid;
        int row = s >> 3;
        int c4 = (s & 7) * 4;
        cp_async16(&Ps[row][c4], &Qg[row * D_HEAD + c4]);
    }
    CP_COMMIT();
    CP_WAIT0();
    __syncthreads();

    unsigned qa[4][4];
#pragma unroll
    for (int kk = 0; kk < 4; kk++) {
        qa[kk][0] = __float_as_uint(Ps[w16 + g    ][kk * 8 + t    ]);
        qa[kk][1] = __float_as_uint(Ps[w16 + g + 8][kk * 8 + t    ]);
        qa[kk][2] = __float_as_uint(Ps[w16 + g    ][kk * 8 + t + 4]);
        qa[kk][3] = __float_as_uint(Ps[w16 + g + 8][kk * 8 + t + 4]);
    }

    float o[4][4];
#pragma unroll
    for (int n = 0; n < 4; n++)
#pragma unroll
        for (int j = 0; j < 4; j++) o[n][j] = 0.0f;

    float m0 = __int_as_float(0xff800000), m1 = m0;
    float l0 = 0.0f, l1 = 0.0f;

    const float* maskp = g_maskval + b * N_SEQ;
    const size_t brow0 = ((size_t)bh * N_SEQ + qb + w16 + g) * N_SEQ;
    const size_t brow1 = brow0 + (size_t)8 * N_SEQ;
    const float* Kg0 = g_K + (size_t)bh * N_SEQ * D_HEAD;
    const float* Vg0 = g_V + (size_t)bh * N_SEQ * D_HEAD;

    for (int kb = 0; kb < N_SEQ; kb += 64) {
        __syncthreads();   // all warps done reading Ks/Vs/Ps of previous tile

        // ---- K/V tile via cp.async (no registers consumed) ----
        const float* Kg = Kg0 + (size_t)kb * D_HEAD;
        const float* Vg = Vg0 + (size_t)kb * D_HEAD;
#pragma unroll
        for (int it = 0; it < 4; it++) {
            int s = it * 128 + tid;
            int row = s >> 3;
            int c4 = (s & 7) * 4;
            cp_async16(&Ks[row][c4], &Kg[row * D_HEAD + c4]);
            cp_async16(&Vs[row][c4], &Vg[row * D_HEAD + c4]);
        }
        CP_COMMIT();

        // ---- bias prefetch: issue all LDGs now, overlap with mma below ----
        float bs[8][4];
#pragma unroll
        for (int n8 = 0; n8 < 8; n8++) {
            const size_t co = (size_t)(kb + n8 * 8 + 2 * t);
            float2 mk = *(const float2*)&maskp[co];
            float2 e0 = *(const float2*)&edge[brow0 + co];
            float2 s0 = *(const float2*)&spat[brow0 + co];
            float2 r0 = *(const float2*)&rnk [brow0 + co];
            float2 e1 = *(const float2*)&edge[brow1 + co];
            float2 s1 = *(const float2*)&spat[brow1 + co];
            float2 r1 = *(const float2*)&rnk [brow1 + co];
            bs[n8][0] = (e0.x + s0.x) + (r0.x + mk.x);
            bs[n8][1] = (e0.y + s0.y) + (r0.y + mk.y);
            bs[n8][2] = (e1.x + s1.x) + (r1.x + mk.x);
            bs[n8][3] = (e1.y + s1.y) + (r1.y + mk.y);
        }

        CP_WAIT0();
        __syncthreads();

        // ---- S = Q K^T (Q pre-scaled) ----
        float sc[8][4];
#pragma unroll
        for (int n8 = 0; n8 < 8; n8++) {
            sc[n8][0] = sc[n8][1] = sc[n8][2] = sc[n8][3] = 0.0f;
#pragma unroll
            for (int kk = 0; kk < 4; kk++) {
                unsigned bb[2];
                bb[0] = __float_as_uint(Ks[n8 * 8 + g][kk * 8 + t    ]);
                bb[1] = __float_as_uint(Ks[n8 * 8 + g][kk * 8 + t + 4]);
                MMA_TF32(sc[n8], qa[kk], bb);
            }
        }

        // ---- add biases+mask ----
#pragma unroll
        for (int n8 = 0; n8 < 8; n8++) {
            sc[n8][0] += bs[n8][0];
            sc[n8][1] += bs[n8][1];
            sc[n8][2] += bs[n8][2];
            sc[n8][3] += bs[n8][3];
        }

        // ---- row maxima ----
        float ml0 = sc[0][0], ml1 = sc[0][2];
#pragma unroll
        for (int n8 = 0; n8 < 8; n8++) {
            ml0 = fmaxf(ml0, fmaxf(sc[n8][0], sc[n8][1]));
            ml1 = fmaxf(ml1, fmaxf(sc[n8][2], sc[n8][3]));
        }
        ml0 = fmaxf(ml0, __shfl_xor_sync(0xffffffffu, ml0, 1));
        ml0 = fmaxf(ml0, __shfl_xor_sync(0xffffffffu, ml0, 2));
        ml1 = fmaxf(ml1, __shfl_xor_sync(0xffffffffu, ml1, 1));
        ml1 = fmaxf(ml1, __shfl_xor_sync(0xffffffffu, ml1, 2));

        float mn0 = fmaxf(m0, ml0);
        float mn1 = fmaxf(m1, ml1);
        float mc0 = fmaxf(mn0, -1e30f);
        float mc1 = fmaxf(mn1, -1e30f);
        float rs0 = __expf(fmaxf(m0, -1e30f) - mc0);
        float rs1 = __expf(fmaxf(m1, -1e30f) - mc1);
        m0 = mn0; m1 = mn1;

        // ---- P = exp(S - m), write to Ps, row sums ----
        float sum0 = 0.0f, sum1 = 0.0f;
#pragma unroll
        for (int n8 = 0; n8 < 8; n8++) {
            float p0 = __expf(sc[n8][0] - mc0);
            float p1 = __expf(sc[n8][1] - mc0);
            float p2 = __expf(sc[n8][2] - mc1);
            float p3 = __expf(sc[n8][3] - mc1);
            sum0 += p0 + p1;
            sum1 += p2 + p3;
            float2 w0, w1;
            w0.x = __uint_as_float(f2tf32(p0)); w0.y = __uint_as_float(f2tf32(p1));
            w1.x = __uint_as_float(f2tf32(p2)); w1.y = __uint_as_float(f2tf32(p3));
            *(float2*)&Ps[w16 + g    ][n8 * 8 + 2 * t] = w0;
            *(float2*)&Ps[w16 + g + 8][n8 * 8 + 2 * t] = w1;
        }
        sum0 += __shfl_xor_sync(0xffffffffu, sum0, 1);
        sum0 += __shfl_xor_sync(0xffffffffu, sum0, 2);
        sum1 += __shfl_xor_sync(0xffffffffu, sum1, 1);
        sum1 += __shfl_xor_sync(0xffffffffu, sum1, 2);
        l0 = l0 * rs0 + sum0;
        l1 = l1 * rs1 + sum1;

        // ---- rescale O ----
#pragma unroll
        for (int n = 0; n < 4; n++) {
            o[n][0] *= rs0; o[n][1] *= rs0;
            o[n][2] *= rs1; o[n][3] *= rs1;
        }

        __syncwarp();

        // ---- O += P V ----
#pragma unroll
        for (int kk = 0; kk < 8; kk++) {
            unsigned pa[4];
            pa[0] = __float_as_uint(Ps[w16 + g    ][kk * 8 + t    ]);
            pa[1] = __float_as_uint(Ps[w16 + g + 8][kk * 8 + t    ]);
            pa[2] = __float_as_uint(Ps[w16 + g    ][kk * 8 + t + 4]);
            pa[3] = __float_as_uint(Ps[w16 + g + 8][kk * 8 + t + 4]);
#pragma unroll
            for (int n = 0; n < 4; n++) {
                unsigned bb[2];
                bb[0] = __float_as_uint(Vs[kk * 8 + t    ][n * 8 + g]);
                bb[1] = __float_as_uint(Vs[kk * 8 + t + 4][n * 8 + g]);
                MMA_TF32(o[n], pa, bb);
            }
        }
    }

    // ---- normalize + scatter (tf32-rounded for the O-projection mma) ----
    float inv0 = (l0 > 0.0f) ? (1.0f / l0) : 0.0f;
    float inv1 = (l1 > 0.0f) ? (1.0f / l1) : 0.0f;
    const int r0 = qb + w16 + g;
    const int r1 = r0 + 8;
#pragma unroll
    for (int n = 0; n < 4; n++) {
        int d = n * 8 + 2 * t;
        float2 v0, v1;
        v0.x = __uint_as_float(f2tf32(o[n][0] * inv0));
        v0.y = __uint_as_float(f2tf32(o[n][1] * inv0));
        v1.x = __uint_as_float(f2tf32(o[n][2] * inv1));
        v1.y = __uint_as_float(f2tf32(o[n][3] * inv1));
        *(float2*)&g_AO[((size_t)(b * N_SEQ + r0)) * D_MODEL + h * D_HEAD + d] = v0;
        *(float2*)&g_AO[((size_t)(b * N_SEQ + r1)) * D_MODEL + h * D_HEAD + d] = v1;
    }
}

// ---------------------------------------------------------------------------
extern "C" void kernel_launch(void* const* d_in, const int* in_sizes, int n_in,
                              void* d_out, int out_size)
{
    const float* x    = (const float*)d_in[0];
    const float* edge = (const float*)d_in[1];
    const float* spat = (const float*)d_in[2];
    const float* rnk  = (const float*)d_in[3];
    const void*  mask = d_in[4];
    const float* Wq = (const float*)d_in[5];
    const float* bq = (const float*)d_in[6];
    const float* Wk = (const float*)d_in[7];
    const float* bk = (const float*)d_in[8];
    const float* Wv = (const float*)d_in[9];
    const float* bv = (const float*)d_in[10];
    const float* Wo = (const float*)d_in[11];
    const float* bo = (const float*)d_in[12];

    prep_mask_kernel<<<1, 256>>>(mask);

    gemm_qkv_tc<<<dim3(64, 4, 3), 128>>>(x, Wq, Wk, Wv, bq, bk, bv);

    attn_tc_kernel<<<dim3(16, 32), 128>>>(edge, spat, rnk);

    gemm_o_tc<<<dim3(64, 4), 128>>>(Wo, bo, (float*)d_out);
}

// round 5
// speedup vs baseline: 2.4809x; 1.1139x over previous
#include <cuda_runtime.h>
#include <math.h>

#define BATCH   4
#define N_SEQ   1024
#define D_MODEL 256
#define N_HEADS 8
#define D_HEAD  32
#define ATT_SCALE 0.17677669529663687f   // 1/sqrt(32)

// Scratch (device globals: no allocation allowed in kernel_launch)
__device__ float g_Q[BATCH * N_HEADS * N_SEQ * D_HEAD];   // [b,h,n,dk]  tf32, pre-scaled
__device__ float g_K[BATCH * N_HEADS * N_SEQ * D_HEAD];   // tf32-rounded
__device__ float g_V[BATCH * N_HEADS * N_SEQ * D_HEAD];   // tf32-rounded
__device__ float g_AO[BATCH * N_SEQ * D_MODEL];           // attention out, tf32-rounded
__device__ float g_maskval[BATCH * N_SEQ];                // 0 or -inf per key

__device__ __forceinline__ unsigned f2tf32(float f) {
    unsigned u;
    asm("cvt.rna.tf32.f32 %0, %1;" : "=r"(u) : "f"(f));
    return u;
}

#define MMA_TF32(d, a, b)                                                     \
    asm volatile(                                                             \
        "mma.sync.aligned.m16n8k8.row.col.f32.tf32.tf32.f32 "                 \
        "{%0,%1,%2,%3}, {%4,%5,%6,%7}, {%8,%9}, {%0,%1,%2,%3};\n"             \
        : "+f"((d)[0]), "+f"((d)[1]), "+f"((d)[2]), "+f"((d)[3])              \
        : "r"((a)[0]), "r"((a)[1]), "r"((a)[2]), "r"((a)[3]),                 \
          "r"((b)[0]), "r"((b)[1]))

__device__ __forceinline__ void cp_async16(void* s, const void* g) {
    unsigned sa = (unsigned)__cvta_generic_to_shared(s);
    asm volatile("cp.async.cg.shared.global [%0], [%1], 16;" :: "r"(sa), "l"(g));
}
#define CP_COMMIT() asm volatile("cp.async.commit_group;")
#define CP_WAIT0()  asm volatile("cp.async.wait_group 0;")
#define CP_WAIT1()  asm volatile("cp.async.wait_group 1;")

// ---------------------------------------------------------------------------
// Mask prep (parallel): detect storage dtype (int32 / float32 / uint8),
// expand to float additive mask (0 or -inf).
// ---------------------------------------------------------------------------
__global__ void prep_mask_kernel(const void* __restrict__ mraw) {
    const int tid = threadIdx.x;   // 256
    const unsigned* mi = (const unsigned*)mraw;
    int ok_int = 1, ok_float = 1;
    for (int i = tid; i < 1024; i += 256) {
        unsigned v = mi[i];
        if (v > 1u) ok_int = 0;
        if (v != 0u && v != 0x3F800000u) ok_float = 0;
    }
    int all_int   = __syncthreads_and(ok_int);
    int all_float = __syncthreads_and(ok_float);
    const int mode = all_int ? 0 : (all_float ? 1 : 2);
    const float NEG_INF = __int_as_float(0xff800000);
    for (int i = tid; i < BATCH * N_SEQ; i += 256) {
        int masked;
        if (mode == 0)      masked = ((const int*)mraw)[i] != 0;
        else if (mode == 1) masked = ((const unsigned*)mraw)[i] != 0u;
        else                masked = ((const unsigned char*)mraw)[i] != 0;
        g_maskval[i] = masked ? NEG_INF : 0.0f;
    }
}

// ---------------------------------------------------------------------------
// Fused QKV projection, tf32 tensor cores, 2-stage cp.async pipeline.
// grid=(64,4,3), block=128. Q additionally scaled by ATT_SCALE.
// ---------------------------------------------------------------------------
__global__ __launch_bounds__(128) void gemm_qkv_tc(
    const float* __restrict__ x,
    const float* __restrict__ Wq, const float* __restrict__ Wk, const float* __restrict__ Wv,
    const float* __restrict__ bq, const float* __restrict__ bk, const float* __restrict__ bv)
{
    __shared__ float As[2][64][36];
    __shared__ float Ws[2][64][36];

    const int z = blockIdx.z;
    const float* W    = (z == 0) ? Wq : (z == 1) ? Wk : Wv;
    const float* bias = (z == 0) ? bq : (z == 1) ? bk : bv;
    float* out        = (z == 0) ? g_Q : (z == 1) ? g_K : g_V;

    const int tid  = threadIdx.x;
    const int lane = tid & 31;
    const int w    = tid >> 5;
    const int g    = lane >> 2;
    const int t    = lane & 3;
    const int w16  = w * 16;
    const int rbase = blockIdx.x * 64;
    const int cbase = blockIdx.y * 64;

    float sc[8][4];
#pragma unroll
    for (int n = 0; n < 8; n++)
#pragma unroll
        for (int j = 0; j < 4; j++) sc[n][j] = 0.0f;

    // stage prefetch of K-chunk c (32 wide)
    auto prefetch = [&](int c) {
        const int k0 = c * 32, st = c & 1;
#pragma unroll
        for (int it = 0; it < 4; it++) {
            int s = it * 128 + tid;
            int row = s >> 3;
            int c4 = (s & 7) * 4;
            cp_async16(&As[st][row][c4], &x[(size_t)(rbase + row) * D_MODEL + k0 + c4]);
        }
#pragma unroll
        for (int it = 0; it < 4; it++) {
            int s = it * 128 + tid;
            int row = s >> 3;
            int c4 = (s & 7) * 4;
            cp_async16(&Ws[st][row][c4], &W[(size_t)(cbase + row) * D_MODEL + k0 + c4]);
        }
        CP_COMMIT();
    };

    prefetch(0);
    for (int c = 0; c < 8; c++) {
        const int st = c & 1;
        if (c < 7) { prefetch(c + 1); CP_WAIT1(); }
        else       { CP_WAIT0(); }
        __syncthreads();

        unsigned qa[4][4];
#pragma unroll
        for (int kk = 0; kk < 4; kk++) {
            qa[kk][0] = f2tf32(As[st][w16 + g    ][kk * 8 + t    ]);
            qa[kk][1] = f2tf32(As[st][w16 + g + 8][kk * 8 + t    ]);
            qa[kk][2] = f2tf32(As[st][w16 + g    ][kk * 8 + t + 4]);
            qa[kk][3] = f2tf32(As[st][w16 + g + 8][kk * 8 + t + 4]);
        }
#pragma unroll
        for (int n8 = 0; n8 < 8; n8++) {
#pragma unroll
            for (int kk = 0; kk < 4; kk++) {
                unsigned bb[2];
                bb[0] = f2tf32(Ws[st][n8 * 8 + g][kk * 8 + t    ]);
                bb[1] = f2tf32(Ws[st][n8 * 8 + g][kk * 8 + t + 4]);
                MMA_TF32(sc[n8], qa[kk], bb);
            }
        }
        __syncthreads();
    }

    const float scale = (z == 0) ? ATT_SCALE : 1.0f;
#pragma unroll
    for (int n8 = 0; n8 < 8; n8++) {
        int c0 = cbase + n8 * 8 + 2 * t;
        float b0v = bias[c0], b1v = bias[c0 + 1];
        int r0 = rbase + w16 + g;
        int r1 = r0 + 8;
        float2 v0, v1;
        v0.x = __uint_as_float(f2tf32((sc[n8][0] + b0v) * scale));
        v0.y = __uint_as_float(f2tf32((sc[n8][1] + b1v) * scale));
        v1.x = __uint_as_float(f2tf32((sc[n8][2] + b0v) * scale));
        v1.y = __uint_as_float(f2tf32((sc[n8][3] + b1v) * scale));
        int h = c0 >> 5, dk = c0 & 31;
        int b0i = r0 >> 10, n0 = r0 & 1023;
        int b1i = r1 >> 10, n1 = r1 & 1023;
        *(float2*)&out[(size_t)(((b0i << 3) + h) * N_SEQ + n0) * D_HEAD + dk] = v0;
        *(float2*)&out[(size_t)(((b1i << 3) + h) * N_SEQ + n1) * D_HEAD + dk] = v1;
    }
}

// ---------------------------------------------------------------------------
// Output projection, tf32 tensor cores, 2-stage cp.async pipeline.
// grid=(64,4), block=128. A = g_AO (already tf32-rounded).
// ---------------------------------------------------------------------------
__global__ __launch_bounds__(128) void gemm_o_tc(
    const float* __restrict__ W, const float* __restrict__ bias,
    float* __restrict__ out)
{
    __shared__ float As[2][64][36];
    __shared__ float Ws[2][64][36];

    const int tid  = threadIdx.x;
    const int lane = tid & 31;
    const int w    = tid >> 5;
    const int g    = lane >> 2;
    const int t    = lane & 3;
    const int w16  = w * 16;
    const int rbase = blockIdx.x * 64;
    const int cbase = blockIdx.y * 64;

    float sc[8][4];
#pragma unroll
    for (int n = 0; n < 8; n++)
#pragma unroll
        for (int j = 0; j < 4; j++) sc[n][j] = 0.0f;

    auto prefetch = [&](int c) {
        const int k0 = c * 32, st = c & 1;
#pragma unroll
        for (int it = 0; it < 4; it++) {
            int s = it * 128 + tid;
            int row = s >> 3;
            int c4 = (s & 7) * 4;
            cp_async16(&As[st][row][c4], &g_AO[(size_t)(rbase + row) * D_MODEL + k0 + c4]);
        }
#pragma unroll
        for (int it = 0; it < 4; it++) {
            int s = it * 128 + tid;
            int row = s >> 3;
            int c4 = (s & 7) * 4;
            cp_async16(&Ws[st][row][c4], &W[(size_t)(cbase + row) * D_MODEL + k0 + c4]);
        }
        CP_COMMIT();
    };

    prefetch(0);
    for (int c = 0; c < 8; c++) {
        const int st = c & 1;
        if (c < 7) { prefetch(c + 1); CP_WAIT1(); }
        else       { CP_WAIT0(); }
        __syncthreads();

        unsigned qa[4][4];
#pragma unroll
        for (int kk = 0; kk < 4; kk++) {
            qa[kk][0] = __float_as_uint(As[st][w16 + g    ][kk * 8 + t    ]);
            qa[kk][1] = __float_as_uint(As[st][w16 + g + 8][kk * 8 + t    ]);
            qa[kk][2] = __float_as_uint(As[st][w16 + g    ][kk * 8 + t + 4]);
            qa[kk][3] = __float_as_uint(As[st][w16 + g + 8][kk * 8 + t + 4]);
        }
#pragma unroll
        for (int n8 = 0; n8 < 8; n8++) {
#pragma unroll
            for (int kk = 0; kk < 4; kk++) {
                unsigned bb[2];
                bb[0] = f2tf32(Ws[st][n8 * 8 + g][kk * 8 + t    ]);
                bb[1] = f2tf32(Ws[st][n8 * 8 + g][kk * 8 + t + 4]);
                MMA_TF32(sc[n8], qa[kk], bb);
            }
        }
        __syncthreads();
    }

#pragma unroll
    for (int n8 = 0; n8 < 8; n8++) {
        int c0 = cbase + n8 * 8 + 2 * t;
        float b0v = bias[c0], b1v = bias[c0 + 1];
        int r0 = rbase + w16 + g;
        int r1 = r0 + 8;
        float2 v0, v1;
        v0.x = sc[n8][0] + b0v;  v0.y = sc[n8][1] + b1v;
        v1.x = sc[n8][2] + b0v;  v1.y = sc[n8][3] + b1v;
        *(float2*)&out[(size_t)r0 * D_MODEL + c0] = v0;
        *(float2*)&out[(size_t)r1 * D_MODEL + c0] = v1;
    }
}

// ---------------------------------------------------------------------------
// Tensor-core flash attention, fully pipelined bias/K/V via cp.async.
// grid=(16,32), block=128 (4 warps). Dynamic smem:
//   Ks[2][64][36]  floats [0, 4608)
//   Vs[2][64][40]  floats [4608, 9728)
//   Ps[64][68]     floats [9728, 14080)
//   BE/BS/BR [64][68] each, floats [14080, 27136)   (bias stage, 1 tile ahead)
// Steady state per k-tile: wait(i) -> S-mma -> bias-combine+softmax -> sync
// -> issue cp.async group(i+1) -> PV-mma.
// ---------------------------------------------------------------------------
#define ATTN_SMEM_BYTES (27136 * 4)

__global__ __launch_bounds__(128) void attn_tc_kernel(
    const float* __restrict__ edge,
    const float* __restrict__ spat,
    const float* __restrict__ rnk)
{
    extern __shared__ float dsm[];
    float* KsB = dsm;                 // 2 * 64*36
    float* VsB = dsm + 4608;          // 2 * 64*40
    float* Ps  = dsm + 9728;          // 64*68
    float* BE  = dsm + 14080;         // 64*68
    float* BS  = BE + 4352;
    float* BR  = BS + 4352;

    const int tid  = threadIdx.x;
    const int lane = tid & 31;
    const int w    = tid >> 5;
    const int g    = lane >> 2;
    const int t    = lane & 3;
    const int qb   = blockIdx.x * 64;
    const int bh   = blockIdx.y;
    const int b    = bh >> 3;
    const int h    = bh & 7;
    const int w16  = w * 16;

    const float* Kg0 = g_K + (size_t)bh * N_SEQ * D_HEAD;
    const float* Vg0 = g_V + (size_t)bh * N_SEQ * D_HEAD;
    const float* maskp = g_maskval + b * N_SEQ;
    const float* eg0 = edge + ((size_t)bh * N_SEQ + qb) * N_SEQ;
    const float* sg0 = spat + ((size_t)bh * N_SEQ + qb) * N_SEQ;
    const float* rg0 = rnk  + ((size_t)bh * N_SEQ + qb) * N_SEQ;

    // issue K/V(0) + bias(0) as one group
    {
        const float* Kg = Kg0;
        const float* Vg = Vg0;
#pragma unroll
        for (int it = 0; it < 4; it++) {
            int s = it * 128 + tid;
            int row = s >> 3;
            int c4 = (s & 7) * 4;
            cp_async16(&KsB[row * 36 + c4], &Kg[row * D_HEAD + c4]);
            cp_async16(&VsB[row * 40 + c4], &Vg[row * D_HEAD + c4]);
        }
#pragma unroll
        for (int it = 0; it < 8; it++) {
            int s = it * 128 + tid;
            int row = s >> 4;
            int c4 = (s & 15) * 4;
            size_t go = (size_t)row * N_SEQ + c4;
            int so = row * 68 + c4;
            cp_async16(&BE[so], &eg0[go]);
            cp_async16(&BS[so], &sg0[go]);
            cp_async16(&BR[so], &rg0[go]);
        }
        CP_COMMIT();
    }

    // stage Q through Ps, extract fragments
    const float* Qg = g_Q + ((size_t)bh * N_SEQ + qb) * D_HEAD;
#pragma unroll
    for (int it = 0; it < 4; it++) {
        int s = it * 128 + tid;
        int row = s >> 3;
        int c4 = (s & 7) * 4;
        cp_async16(&Ps[row * 68 + c4], &Qg[row * D_HEAD + c4]);
    }
    CP_COMMIT();
    CP_WAIT0();
    __syncthreads();

    unsigned qa[4][4];
#pragma unroll
    for (int kk = 0; kk < 4; kk++) {
        qa[kk][0] = __float_as_uint(Ps[(w16 + g    ) * 68 + kk * 8 + t    ]);
        qa[kk][1] = __float_as_uint(Ps[(w16 + g + 8) * 68 + kk * 8 + t    ]);
        qa[kk][2] = __float_as_uint(Ps[(w16 + g    ) * 68 + kk * 8 + t + 4]);
        qa[kk][3] = __float_as_uint(Ps[(w16 + g + 8) * 68 + kk * 8 + t + 4]);
    }

    // mask regs for tile 0
    float2 mkc[8];
#pragma unroll
    for (int n8 = 0; n8 < 8; n8++)
        mkc[n8] = *(const float2*)&maskp[n8 * 8 + 2 * t];

    float o[4][4];
#pragma unroll
    for (int n = 0; n < 4; n++)
#pragma unroll
        for (int j = 0; j < 4; j++) o[n][j] = 0.0f;

    float m0 = __int_as_float(0xff800000), m1 = m0;
    float l0 = 0.0f, l1 = 0.0f;

    for (int i = 0; i < 16; i++) {
        const int kb = i * 64;
        const int cur = i & 1;
        float* Ks = KsB + cur * 2304;
        float* Vs = VsB + cur * 2560;

        // 1. group(i) arrived; also: every warp finished tile i-1 entirely
        CP_WAIT0();
        __syncthreads();

        // 2. S = Q K^T (Q pre-scaled by ATT_SCALE)
        float sc[8][4];
#pragma unroll
        for (int n8 = 0; n8 < 8; n8++) {
            sc[n8][0] = sc[n8][1] = sc[n8][2] = sc[n8][3] = 0.0f;
#pragma unroll
            for (int kk = 0; kk < 4; kk++) {
                unsigned bb[2];
                bb[0] = __float_as_uint(Ks[(n8 * 8 + g) * 36 + kk * 8 + t    ]);
                bb[1] = __float_as_uint(Ks[(n8 * 8 + g) * 36 + kk * 8 + t + 4]);
                MMA_TF32(sc[n8], qa[kk], bb);
            }
        }

        // 3. combine biases (from smem stage) + mask (regs)
#pragma unroll
        for (int n8 = 0; n8 < 8; n8++) {
            int c0 = n8 * 8 + 2 * t;
            int ro0 = (w16 + g    ) * 68 + c0;
            int ro1 = (w16 + g + 8) * 68 + c0;
            float2 e0 = *(float2*)&BE[ro0], e1 = *(float2*)&BE[ro1];
            float2 s0 = *(float2*)&BS[ro0], s1 = *(float2*)&BS[ro1];
            float2 r0 = *(float2*)&BR[ro0], r1 = *(float2*)&BR[ro1];
            float2 mk = mkc[n8];
            sc[n8][0] += (e0.x + s0.x) + (r0.x + mk.x);
            sc[n8][1] += (e0.y + s0.y) + (r0.y + mk.y);
            sc[n8][2] += (e1.x + s1.x) + (r1.x + mk.x);
            sc[n8][3] += (e1.y + s1.y) + (r1.y + mk.y);
        }

        // online softmax
        float ml0 = sc[0][0], ml1 = sc[0][2];
#pragma unroll
        for (int n8 = 0; n8 < 8; n8++) {
            ml0 = fmaxf(ml0, fmaxf(sc[n8][0], sc[n8][1]));
            ml1 = fmaxf(ml1, fmaxf(sc[n8][2], sc[n8][3]));
        }
        ml0 = fmaxf(ml0, __shfl_xor_sync(0xffffffffu, ml0, 1));
        ml0 = fmaxf(ml0, __shfl_xor_sync(0xffffffffu, ml0, 2));
        ml1 = fmaxf(ml1, __shfl_xor_sync(0xffffffffu, ml1, 1));
        ml1 = fmaxf(ml1, __shfl_xor_sync(0xffffffffu, ml1, 2));

        float mn0 = fmaxf(m0, ml0);
        float mn1 = fmaxf(m1, ml1);
        float mc0 = fmaxf(mn0, -1e30f);
        float mc1 = fmaxf(mn1, -1e30f);
        float rs0 = __expf(fmaxf(m0, -1e30f) - mc0);
        float rs1 = __expf(fmaxf(m1, -1e30f) - mc1);
        m0 = mn0; m1 = mn1;

        float sum0 = 0.0f, sum1 = 0.0f;
#pragma unroll
        for (int n8 = 0; n8 < 8; n8++) {
            float p0 = __expf(sc[n8][0] - mc0);
            float p1 = __expf(sc[n8][1] - mc0);
            float p2 = __expf(sc[n8][2] - mc1);
            float p3 = __expf(sc[n8][3] - mc1);
            sum0 += p0 + p1;
            sum1 += p2 + p3;
            float2 w0, w1;
            w0.x = __uint_as_float(f2tf32(p0)); w0.y = __uint_as_float(f2tf32(p1));
            w1.x = __uint_as_float(f2tf32(p2)); w1.y = __uint_as_float(f2tf32(p3));
            *(float2*)&Ps[(w16 + g    ) * 68 + n8 * 8 + 2 * t] = w0;
            *(float2*)&Ps[(w16 + g + 8) * 68 + n8 * 8 + 2 * t] = w1;
        }
        sum0 += __shfl_xor_sync(0xffffffffu, sum0, 1);
        sum0 += __shfl_xor_sync(0xffffffffu, sum0, 2);
        sum1 += __shfl_xor_sync(0xffffffffu, sum1, 1);
        sum1 += __shfl_xor_sync(0xffffffffu, sum1, 2);
        l0 = l0 * rs0 + sum0;
        l1 = l1 * rs1 + sum1;

#pragma unroll
        for (int n = 0; n < 4; n++) {
            o[n][0] *= rs0; o[n][1] *= rs0;
            o[n][2] *= rs1; o[n][3] *= rs1;
        }

        // 4. all warps done with bias stage (and prior alt K/V)
        __syncthreads();

        // 5. issue group(i+1): K/V into alt stage, biases into stage, mask regs
        if (i < 15) {
            const int kbn = kb + 64;
            const int alt = 1 - cur;
            const float* Kg = Kg0 + (size_t)kbn * D_HEAD;
            const float* Vg = Vg0 + (size_t)kbn * D_HEAD;
            float* Ka = KsB + alt * 2304;
            float* Va = VsB + alt * 2560;
#pragma unroll
            for (int it = 0; it < 4; it++) {
                int s = it * 128 + tid;
                int row = s >> 3;
                int c4 = (s & 7) * 4;
                cp_async16(&Ka[row * 36 + c4], &Kg[row * D_HEAD + c4]);
                cp_async16(&Va[row * 40 + c4], &Vg[row * D_HEAD + c4]);
            }
            const float* eg = eg0 + kbn;
            const float* sg = sg0 + kbn;
            const float* rg = rg0 + kbn;
#pragma unroll
            for (int it = 0; it < 8; it++) {
                int s = it * 128 + tid;
                int row = s >> 4;
                int c4 = (s & 15) * 4;
                size_t go = (size_t)row * N_SEQ + c4;
                int so = row * 68 + c4;
                cp_async16(&BE[so], &eg[go]);
                cp_async16(&BS[so], &sg[go]);
                cp_async16(&BR[so], &rg[go]);
            }
            CP_COMMIT();
#pragma unroll
            for (int n8 = 0; n8 < 8; n8++)
                mkc[n8] = *(const float2*)&maskp[kbn + n8 * 8 + 2 * t];
        }

        __syncwarp();   // this warp's Ps rows visible warp-wide

        // 6. O += P V
#pragma unroll
        for (int kk = 0; kk < 8; kk++) {
            unsigned pa[4];
            pa[0] = __float_as_uint(Ps[(w16 + g    ) * 68 + kk * 8 + t    ]);
            pa[1] = __float_as_uint(Ps[(w16 + g + 8) * 68 + kk * 8 + t    ]);
            pa[2] = __float_as_uint(Ps[(w16 + g    ) * 68 + kk * 8 + t + 4]);
            pa[3] = __float_as_uint(Ps[(w16 + g + 8) * 68 + kk * 8 + t + 4]);
#pragma unroll
            for (int n = 0; n < 4; n++) {
                unsigned bb[2];
                bb[0] = __float_as_uint(Vs[(kk * 8 + t    ) * 40 + n * 8 + g]);
                bb[1] = __float_as_uint(Vs[(kk * 8 + t + 4) * 40 + n * 8 + g]);
                MMA_TF32(o[n], pa, bb);
            }
        }
    }

    // normalize + scatter (tf32-rounded for the O-projection mma)
    float inv0 = (l0 > 0.0f) ? (1.0f / l0) : 0.0f;
    float inv1 = (l1 > 0.0f) ? (1.0f / l1) : 0.0f;
    const int r0 = qb + w16 + g;
    const int r1 = r0 + 8;
#pragma unroll
    for (int n = 0; n < 4; n++) {
        int d = n * 8 + 2 * t;
        float2 v0, v1;
        v0.x = __uint_as_float(f2tf32(o[n][0] * inv0));
        v0.y = __uint_as_float(f2tf32(o[n][1] * inv0));
        v1.x = __uint_as_float(f2tf32(o[n][2] * inv1));
        v1.y = __uint_as_float(f2tf32(o[n][3] * inv1));
        *(float2*)&g_AO[((size_t)(b * N_SEQ + r0)) * D_MODEL + h * D_HEAD + d] = v0;
        *(float2*)&g_AO[((size_t)(b * N_SEQ + r1)) * D_MODEL + h * D_HEAD + d] = v1;
    }
}

// ---------------------------------------------------------------------------
extern "C" void kernel_launch(void* const* d_in, const int* in_sizes, int n_in,
                              void* d_out, int out_size)
{
    const float* x    = (const float*)d_in[0];
    const float* edge = (const float*)d_in[1];
    const float* spat = (const float*)d_in[2];
    const float* rnk  = (const float*)d_in[3];
    const void*  mask = d_in[4];
    const float* Wq = (const float*)d_in[5];
    const float* bq = (const float*)d_in[6];
    const float* Wk = (const float*)d_in[7];
    const float* bk = (const float*)d_in[8];
    const float* Wv = (const float*)d_in[9];
    const float* bv = (const float*)d_in[10];
    const float* Wo = (const float*)d_in[11];
    const float* bo = (const float*)d_in[12];

    cudaFuncSetAttribute(attn_tc_kernel,
                         cudaFuncAttributeMaxDynamicSharedMemorySize,
                         ATTN_SMEM_BYTES);

    prep_mask_kernel<<<1, 256>>>(mask);

    gemm_qkv_tc<<<dim3(64, 4, 3), 128>>>(x, Wq, Wk, Wv, bq, bk, bv);

    attn_tc_kernel<<<dim3(16, 32), 128, ATTN_SMEM_BYTES>>>(edge, spat, rnk);

    gemm_o_tc<<<dim3(64, 4), 128>>>(Wo, bo, (float*)d_out);
}